// round 5
// baseline (speedup 1.0000x reference)
#include <cuda_runtime.h>
#include <cstdint>

// ---------------------------------------------------------------------------
// PingHead on sm_103 (legacy mma.sync tf32 path).
// gi = x @ W_ih^T : M=65536, N=384, K=1024 ; fused GRU-gate epilogue.
// R5: 512 threads / 16 warps (4 per SMSP), warp grid 2m x 8n (64m x 48n per
// warp), 96 accum regs/thread. W pre-rounded to tf32; A raw fp32 (HMMA
// truncation, rel_err 4.3e-4 measured).
// ---------------------------------------------------------------------------

#define KCHUNKS 32
#define A_BYTES (128 * 128)                 // 128 rows x 32 f32
#define B_BYTES (384 * 128)                 // 384 rows x 32 f32
#define STAGE_BYTES (A_BYTES + B_BYTES)     // 64 KB
#define ROWP 385                            // gi row stride (floats)
#define GI_BYTES (128 * ROWP * 4)
#define SMEM_DYN (GI_BYTES + 1024)

__device__ float g_wtf32[384 * 1024];       // W_ih pre-rounded to tf32

__device__ __forceinline__ uint32_t smem_u32(const void* p) {
    uint32_t a;
    asm("{ .reg .u64 t; cvta.to.shared.u64 t, %1; cvt.u32.u64 %0, t; }" : "=r"(a) : "l"(p));
    return a;
}

__device__ __forceinline__ void cp_async16(uint32_t dst, const void* src) {
    asm volatile("cp.async.cg.shared.global [%0], [%1], 16;" :: "r"(dst), "l"(src) : "memory");
}
#define CP_COMMIT() asm volatile("cp.async.commit_group;" ::: "memory")
#define CP_WAIT1()  asm volatile("cp.async.wait_group 1;" ::: "memory")
#define CP_WAIT0()  asm volatile("cp.async.wait_group 0;" ::: "memory")

__device__ __forceinline__ void ldsm4(uint32_t* r, uint32_t addr) {
    asm volatile("ldmatrix.sync.aligned.m8n8.x4.shared.b16 {%0,%1,%2,%3}, [%4];"
                 : "=r"(r[0]), "=r"(r[1]), "=r"(r[2]), "=r"(r[3]) : "r"(addr));
}

__device__ __forceinline__ uint32_t cvt_tf32f(float f) {
    uint32_t r;
    asm("cvt.rna.tf32.f32 %0, %1;" : "=r"(r) : "f"(f));
    return r;
}

__device__ __forceinline__ void mma_tf32(float* d, const uint32_t* a, const uint32_t* b) {
    asm volatile("mma.sync.aligned.m16n8k8.row.col.f32.tf32.tf32.f32 "
                 "{%0,%1,%2,%3},{%4,%5,%6,%7},{%8,%9},{%0,%1,%2,%3};"
                 : "+f"(d[0]), "+f"(d[1]), "+f"(d[2]), "+f"(d[3])
                 : "r"(a[0]), "r"(a[1]), "r"(a[2]), "r"(a[3]), "r"(b[0]), "r"(b[1]));
}

// --- pre-kernel: round W to tf32 with rna (runs once per replay, ~2us) ---
__global__ void __launch_bounds__(256) wconv_kernel(const float* __restrict__ w) {
    const int i = (blockIdx.x * 256 + threadIdx.x) * 4;
    const float4 v = *reinterpret_cast<const float4*>(w + i);
    uint4 o = make_uint4(cvt_tf32f(v.x), cvt_tf32f(v.y), cvt_tf32f(v.z), cvt_tf32f(v.w));
    *reinterpret_cast<uint4*>(g_wtf32 + i) = o;
}

__global__ void __launch_bounds__(512, 1)
ping_head_kernel(const float* __restrict__ x,
                 const float* __restrict__ b_ih,
                 const float* __restrict__ b_hh,
                 const float* __restrict__ lin_w,
                 const float* __restrict__ lin_b,
                 float* __restrict__ out) {
    extern __shared__ char dsm[];
    __shared__ float s_br[128], s_bz[128], s_bni[128], s_bnh[128], s_lw[128];

    const int tid = threadIdx.x;
    const int wid = tid >> 5;
    const int lane = tid & 31;
    const int m0 = blockIdx.x * 128;

    const uint32_t dsm_u = smem_u32(dsm);
    const uint32_t sb = (dsm_u + 1023u) & ~1023u;   // 1KB-aligned smem base
    char* sb_ptr = dsm + (sb - dsm_u);

    if (tid < 128) {
        s_br[tid]  = b_ih[tid] + b_hh[tid];
        s_bz[tid]  = b_ih[128 + tid] + b_hh[128 + tid];
        s_bni[tid] = b_ih[256 + tid];
        s_bnh[tid] = b_hh[256 + tid];
        s_lw[tid]  = lin_w[tid];
    }

    // ---- stage copy: raw cp.async for A (fp32) and B (pre-tf32), 512 thr ----
    auto copy_stage = [&](int kc) {
        const uint32_t sbase = sb + (uint32_t)(kc % 3) * STAGE_BYTES;
        const int koff = kc * 32;
#pragma unroll
        for (int ch = 0; ch < 8; ch++) {
            const int idx = tid + ch * 512;
            if (idx < 1024) {                      // A: 128 rows x 8 chunks
                const int row = idx >> 3, c = idx & 7;
                const float* src = x + (size_t)(m0 + row) * 1024 + koff + c * 4;
                const uint32_t doff = (uint32_t)(row * 128) +
                                      (((uint32_t)(c * 16)) ^ ((uint32_t)(row & 7) << 4));
                cp_async16(sbase + doff, src);
            } else {                               // B: 384 rows x 8 chunks
                const int bi = idx - 1024;
                const int row = bi >> 3, c = bi & 7;
                const float* src = g_wtf32 + (size_t)row * 1024 + koff + c * 4;
                const uint32_t doff = (uint32_t)A_BYTES + (uint32_t)(row * 128) +
                                      (((uint32_t)(c * 16)) ^ ((uint32_t)(row & 7) << 4));
                cp_async16(sbase + doff, src);
            }
        }
    };

    // ---- per-thread ldmatrix addressing (2m x 8n warp grid, 16 warps) ----
    const int warp_m = wid >> 3;          // 0..1 -> 64 rows each
    const int warp_n = wid & 7;           // 0..7 -> 48 cols each (6 n8 tiles)
    const int mb = warp_m * 64;
    const int nb = warp_n * 48;

    const int ri = lane & 15;
    const uint32_t sega = (uint32_t)((lane >> 4) << 4);
    const uint32_t xpa  = (uint32_t)((ri & 7) << 4);
    const uint32_t a_root = (uint32_t)((mb + ri) * 128);

    const int rb = (lane & 7) + (((lane >> 4) & 1) << 3);
    const uint32_t segb = (uint32_t)(((lane >> 3) & 1) << 4);
    const uint32_t xpb  = (uint32_t)((rb & 7) << 4);
    const uint32_t b_root = (uint32_t)A_BYTES + (uint32_t)((nb + rb) * 128);

    float acc[4][6][4];
#pragma unroll
    for (int t = 0; t < 4; t++)
#pragma unroll
        for (int j = 0; j < 6; j++)
#pragma unroll
            for (int q = 0; q < 4; q++) acc[t][j][q] = 0.0f;

    copy_stage(0); CP_COMMIT();
    copy_stage(1); CP_COMMIT();

    for (int kc = 0; kc < KCHUNKS; kc++) {
        CP_WAIT1();
        __syncthreads();
        if (kc + 2 < KCHUNKS) copy_stage(kc + 2);
        CP_COMMIT();

        const uint32_t stb = sb + (uint32_t)(kc % 3) * STAGE_BYTES;
#pragma unroll
        for (int s = 0; s < 4; s++) {
            const uint32_t sbytes = (uint32_t)(s * 32);
            uint32_t bf[3][4];
#pragma unroll
            for (int jp = 0; jp < 3; jp++) {
                ldsm4(bf[jp], stb + b_root + (uint32_t)(jp * 2048) + ((sbytes + segb) ^ xpb));
            }
#pragma unroll
            for (int t = 0; t < 4; t++) {
                uint32_t af[4];
                ldsm4(af, stb + a_root + (uint32_t)(t * 2048) + ((sbytes + sega) ^ xpa));
#pragma unroll
                for (int j = 0; j < 6; j++) {
                    mma_tf32(acc[t][j], af, &bf[j >> 1][(j & 1) * 2]);
                }
            }
        }
    }

    CP_WAIT0();
    __syncthreads();

    // ---- spill gi to smem ----
    float* gi = reinterpret_cast<float*>(sb_ptr);
    {
        const int r0 = mb + (lane >> 2);
        const int c0 = nb + 2 * (lane & 3);
#pragma unroll
        for (int t = 0; t < 4; t++) {
            const int row = r0 + t * 16;
#pragma unroll
            for (int j = 0; j < 6; j++) {
                const int col = c0 + j * 8;
                gi[row * ROWP + col]           = acc[t][j][0];
                gi[row * ROWP + col + 1]       = acc[t][j][1];
                gi[(row + 8) * ROWP + col]     = acc[t][j][2];
                gi[(row + 8) * ROWP + col + 1] = acc[t][j][3];
            }
        }
    }
    __syncthreads();

    // ---- fused gate epilogue: 4 threads per row ----
    {
        const int row = tid >> 2;
        const int qtr = tid & 3;
        const float* gr = gi + row * ROWP;
        float a = 0.0f;
#pragma unroll 4
        for (int k = 0; k < 32; k++) {
            const int g = qtr * 32 + k;
            const float xr = gr[g] + s_br[g];
            const float xz = gr[128 + g] + s_bz[g];
            const float r  = 1.0f / (1.0f + __expf(-xr));
            const float zc = 1.0f / (1.0f + __expf(xz));          // 1 - z
            const float xn = gr[256 + g] + s_bni[g] + r * s_bnh[g];
            const float e  = __expf(-2.0f * fabsf(xn));
            float th = __fdividef(1.0f - e, 1.0f + e);
            th = copysignf(th, xn);
            a += s_lw[g] * zc * th;
        }
        a += __shfl_xor_sync(0xffffffffu, a, 1);
        a += __shfl_xor_sync(0xffffffffu, a, 2);
        if (qtr == 0) out[m0 + row] = a + lin_b[0];
    }
}

extern "C" void kernel_launch(void* const* d_in, const int* in_sizes, int n_in,
                              void* d_out, int out_size) {
    const float* x     = (const float*)d_in[0];
    const float* w_ih  = (const float*)d_in[1];
    // d_in[2] = weight_hh: mathematically dead (hidden state is always zero)
    const float* b_ih  = (const float*)d_in[3];
    const float* b_hh  = (const float*)d_in[4];
    const float* lin_w = (const float*)d_in[5];
    const float* lin_b = (const float*)d_in[6];
    float* out = (float*)d_out;

    wconv_kernel<<<384, 256>>>(w_ih);   // 384*1024 floats / (256*4)

    cudaFuncSetAttribute(ping_head_kernel,
                         cudaFuncAttributeMaxDynamicSharedMemorySize, SMEM_DYN);
    ping_head_kernel<<<512, 512, SMEM_DYN>>>(x, b_ih, b_hh, lin_w, lin_b, out);
}

// round 6
// speedup vs baseline: 1.0455x; 1.0455x over previous
#include <cuda_runtime.h>
#include <cstdint>

// ---------------------------------------------------------------------------
// PingHead on sm_103 (legacy mma.sync tf32 path).
// gi = x @ W_ih^T : M=65536, N=384, K=1024 ; fused GRU-gate epilogue.
// R6: R4 config (256 thr, 2m x 4n, 192 acc regs) + A-fragment ping-pong
// prefetch across t-steps and s-steps to hide LDS latency behind MMAs.
// W pre-rounded to tf32 (rna); A raw fp32 (HMMA truncation).
// ---------------------------------------------------------------------------

#define KCHUNKS 32
#define A_BYTES (128 * 128)                 // 128 rows x 32 f32
#define B_BYTES (384 * 128)                 // 384 rows x 32 f32
#define STAGE_BYTES (A_BYTES + B_BYTES)     // 64 KB
#define ROWP 385                            // gi row stride (floats)
#define GI_BYTES (128 * ROWP * 4)
#define SMEM_DYN (GI_BYTES + 1024)

__device__ float g_wtf32[384 * 1024];       // W_ih pre-rounded to tf32

__device__ __forceinline__ uint32_t smem_u32(const void* p) {
    uint32_t a;
    asm("{ .reg .u64 t; cvta.to.shared.u64 t, %1; cvt.u32.u64 %0, t; }" : "=r"(a) : "l"(p));
    return a;
}

__device__ __forceinline__ void cp_async16(uint32_t dst, const void* src) {
    asm volatile("cp.async.cg.shared.global [%0], [%1], 16;" :: "r"(dst), "l"(src) : "memory");
}
#define CP_COMMIT() asm volatile("cp.async.commit_group;" ::: "memory")
#define CP_WAIT1()  asm volatile("cp.async.wait_group 1;" ::: "memory")
#define CP_WAIT0()  asm volatile("cp.async.wait_group 0;" ::: "memory")

__device__ __forceinline__ void ldsm4(uint32_t* r, uint32_t addr) {
    asm volatile("ldmatrix.sync.aligned.m8n8.x4.shared.b16 {%0,%1,%2,%3}, [%4];"
                 : "=r"(r[0]), "=r"(r[1]), "=r"(r[2]), "=r"(r[3]) : "r"(addr));
}

__device__ __forceinline__ uint32_t cvt_tf32f(float f) {
    uint32_t r;
    asm("cvt.rna.tf32.f32 %0, %1;" : "=r"(r) : "f"(f));
    return r;
}

__device__ __forceinline__ void mma_tf32(float* d, const uint32_t* a, const uint32_t* b) {
    asm volatile("mma.sync.aligned.m16n8k8.row.col.f32.tf32.tf32.f32 "
                 "{%0,%1,%2,%3},{%4,%5,%6,%7},{%8,%9},{%0,%1,%2,%3};"
                 : "+f"(d[0]), "+f"(d[1]), "+f"(d[2]), "+f"(d[3])
                 : "r"(a[0]), "r"(a[1]), "r"(a[2]), "r"(a[3]), "r"(b[0]), "r"(b[1]));
}

// --- pre-kernel: round W to tf32 with rna (runs once per replay, ~2us) ---
__global__ void __launch_bounds__(256) wconv_kernel(const float* __restrict__ w) {
    const int i = (blockIdx.x * 256 + threadIdx.x) * 4;
    const float4 v = *reinterpret_cast<const float4*>(w + i);
    uint4 o = make_uint4(cvt_tf32f(v.x), cvt_tf32f(v.y), cvt_tf32f(v.z), cvt_tf32f(v.w));
    *reinterpret_cast<uint4*>(g_wtf32 + i) = o;
}

__global__ void __launch_bounds__(256, 1)
ping_head_kernel(const float* __restrict__ x,
                 const float* __restrict__ b_ih,
                 const float* __restrict__ b_hh,
                 const float* __restrict__ lin_w,
                 const float* __restrict__ lin_b,
                 float* __restrict__ out) {
    extern __shared__ char dsm[];
    __shared__ float s_br[128], s_bz[128], s_bni[128], s_bnh[128], s_lw[128];

    const int tid = threadIdx.x;
    const int wid = tid >> 5;
    const int lane = tid & 31;
    const int m0 = blockIdx.x * 128;

    const uint32_t dsm_u = smem_u32(dsm);
    const uint32_t sb = (dsm_u + 1023u) & ~1023u;   // 1KB-aligned smem base
    char* sb_ptr = dsm + (sb - dsm_u);

    if (tid < 128) {
        s_br[tid]  = b_ih[tid] + b_hh[tid];
        s_bz[tid]  = b_ih[128 + tid] + b_hh[128 + tid];
        s_bni[tid] = b_ih[256 + tid];
        s_bnh[tid] = b_hh[256 + tid];
        s_lw[tid]  = lin_w[tid];
    }

    // ---- stage copy: raw cp.async for A (fp32) and B (pre-tf32) ----
    auto copy_stage = [&](int kc) {
        const uint32_t sbase = sb + (uint32_t)(kc % 3) * STAGE_BYTES;
        const int koff = kc * 32;
#pragma unroll
        for (int ch = 0; ch < 16; ch++) {
            const int idx = tid + ch * 256;
            if (idx < 1024) {                      // A: 128 rows x 8 chunks
                const int row = idx >> 3, c = idx & 7;
                const float* src = x + (size_t)(m0 + row) * 1024 + koff + c * 4;
                const uint32_t doff = (uint32_t)(row * 128) +
                                      (((uint32_t)(c * 16)) ^ ((uint32_t)(row & 7) << 4));
                cp_async16(sbase + doff, src);
            } else {                               // B: 384 rows x 8 chunks
                const int bi = idx - 1024;
                const int row = bi >> 3, c = bi & 7;
                const float* src = g_wtf32 + (size_t)row * 1024 + koff + c * 4;
                const uint32_t doff = (uint32_t)A_BYTES + (uint32_t)(row * 128) +
                                      (((uint32_t)(c * 16)) ^ ((uint32_t)(row & 7) << 4));
                cp_async16(sbase + doff, src);
            }
        }
    };

    // ---- per-thread ldmatrix addressing (2m x 4n warp grid) ----
    const int warp_m = wid >> 2;
    const int warp_n = wid & 3;
    const int mb = warp_m * 64;
    const int nb = warp_n * 96;

    const int ri = lane & 15;
    const uint32_t sega = (uint32_t)((lane >> 4) << 4);
    const uint32_t xpa  = (uint32_t)((ri & 7) << 4);
    const uint32_t a_root = (uint32_t)((mb + ri) * 128);

    const int rb = (lane & 7) + (((lane >> 4) & 1) << 3);
    const uint32_t segb = (uint32_t)(((lane >> 3) & 1) << 4);
    const uint32_t xpb  = (uint32_t)((rb & 7) << 4);
    const uint32_t b_root = (uint32_t)A_BYTES + (uint32_t)((nb + rb) * 128);

    float acc[4][12][4];
#pragma unroll
    for (int t = 0; t < 4; t++)
#pragma unroll
        for (int j = 0; j < 12; j++)
#pragma unroll
            for (int q = 0; q < 4; q++) acc[t][j][q] = 0.0f;

    copy_stage(0); CP_COMMIT();
    copy_stage(1); CP_COMMIT();

    for (int kc = 0; kc < KCHUNKS; kc++) {
        CP_WAIT1();
        __syncthreads();
        if (kc + 2 < KCHUNKS) copy_stage(kc + 2);
        CP_COMMIT();

        const uint32_t stb = sb + (uint32_t)(kc % 3) * STAGE_BYTES;

        // A-fragment ping-pong: af[par] in use, af[par^1] being prefetched.
        uint32_t af[2][4];
        ldsm4(af[0], stb + a_root + ((0u + sega) ^ xpa));   // (t=0, s=0)

#pragma unroll
        for (int s = 0; s < 4; s++) {
            const uint32_t sbytes = (uint32_t)(s * 32);
            uint32_t bf[6][4];
#pragma unroll
            for (int jp = 0; jp < 6; jp++) {
                ldsm4(bf[jp], stb + b_root + (uint32_t)(jp * 2048) + ((sbytes + segb) ^ xpb));
            }
#pragma unroll
            for (int t = 0; t < 4; t++) {
                const int par = (s * 4 + t) & 1;
                // prefetch next af: (t+1, s) or (0, s+1); none after last step
                if (t < 3) {
                    ldsm4(af[par ^ 1], stb + a_root + (uint32_t)((t + 1) * 2048) + ((sbytes + sega) ^ xpa));
                } else if (s < 3) {
                    ldsm4(af[par ^ 1], stb + a_root + (((sbytes + 32u) + sega) ^ xpa));
                }
#pragma unroll
                for (int j = 0; j < 12; j++) {
                    mma_tf32(acc[t][j], af[par], &bf[j >> 1][(j & 1) * 2]);
                }
            }
        }
    }

    CP_WAIT0();
    __syncthreads();

    // ---- spill gi to smem ----
    float* gi = reinterpret_cast<float*>(sb_ptr);
    {
        const int r0 = mb + (lane >> 2);
        const int c0 = nb + 2 * (lane & 3);
#pragma unroll
        for (int t = 0; t < 4; t++) {
            const int row = r0 + t * 16;
#pragma unroll
            for (int j = 0; j < 12; j++) {
                const int col = c0 + j * 8;
                gi[row * ROWP + col]           = acc[t][j][0];
                gi[row * ROWP + col + 1]       = acc[t][j][1];
                gi[(row + 8) * ROWP + col]     = acc[t][j][2];
                gi[(row + 8) * ROWP + col + 1] = acc[t][j][3];
            }
        }
    }
    __syncthreads();

    // ---- fused gate epilogue: 2 threads per row ----
    {
        const int row = tid >> 1;
        const int half = tid & 1;
        const float* gr = gi + row * ROWP;
        float a = 0.0f;
#pragma unroll 4
        for (int k = 0; k < 64; k++) {
            const int g = 2 * k + half;
            const float xr = gr[g] + s_br[g];
            const float xz = gr[128 + g] + s_bz[g];
            const float r  = 1.0f / (1.0f + __expf(-xr));
            const float zc = 1.0f / (1.0f + __expf(xz));          // 1 - z
            const float xn = gr[256 + g] + s_bni[g] + r * s_bnh[g];
            const float e  = __expf(-2.0f * fabsf(xn));
            float th = __fdividef(1.0f - e, 1.0f + e);
            th = copysignf(th, xn);
            a += s_lw[g] * zc * th;
        }
        a += __shfl_xor_sync(0xffffffffu, a, 1);
        if (half == 0) out[m0 + row] = a + lin_b[0];
    }
}

extern "C" void kernel_launch(void* const* d_in, const int* in_sizes, int n_in,
                              void* d_out, int out_size) {
    const float* x     = (const float*)d_in[0];
    const float* w_ih  = (const float*)d_in[1];
    // d_in[2] = weight_hh: mathematically dead (hidden state is always zero)
    const float* b_ih  = (const float*)d_in[3];
    const float* b_hh  = (const float*)d_in[4];
    const float* lin_w = (const float*)d_in[5];
    const float* lin_b = (const float*)d_in[6];
    float* out = (float*)d_out;

    wconv_kernel<<<384, 256>>>(w_ih);   // 384*1024 floats / (256*4)

    cudaFuncSetAttribute(ping_head_kernel,
                         cudaFuncAttributeMaxDynamicSharedMemorySize, SMEM_DYN);
    ping_head_kernel<<<512, 256, SMEM_DYN>>>(x, b_ih, b_hh, lin_w, lin_b, out);
}

// round 7
// speedup vs baseline: 1.0822x; 1.0351x over previous
#include <cuda_runtime.h>
#include <cuda_fp16.h>
#include <cstdint>

// ---------------------------------------------------------------------------
// PingHead on sm_103 (legacy mma.sync path).
// gi = x @ W_ih^T : M=65536, N=384, K=1024 ; fused GRU-gate epilogue.
// R7: fp16 operands (same 10-bit mantissa as tf32 -> same precision), fp32
// accumulate. mma.m16n8k16 halves HMMA count vs tf32 k8. W pre-converted to
// fp16 once; x converted LDG->cvt->STS inside copy_stage (transient regs).
// 256 thr, 2m x 4n warp grid, K chunk = 64 (16 chunks), 3-stage ring.
// ---------------------------------------------------------------------------

#define KCHUNKS 16
#define A_BYTES (128 * 128)                 // 128 rows x 64 halves
#define B_BYTES (384 * 128)                 // 384 rows x 64 halves
#define STAGE_BYTES (A_BYTES + B_BYTES)     // 64 KB
#define ROWP 385                            // gi row stride (floats)
#define GI_BYTES (128 * ROWP * 4)
#define SMEM_DYN (GI_BYTES + 1024)

__device__ __half g_wh[384 * 1024];         // W_ih pre-converted to fp16 (rne)

__device__ __forceinline__ uint32_t smem_u32(const void* p) {
    uint32_t a;
    asm("{ .reg .u64 t; cvta.to.shared.u64 t, %1; cvt.u32.u64 %0, t; }" : "=r"(a) : "l"(p));
    return a;
}

__device__ __forceinline__ void cp_async16(uint32_t dst, const void* src) {
    asm volatile("cp.async.cg.shared.global [%0], [%1], 16;" :: "r"(dst), "l"(src) : "memory");
}
#define CP_COMMIT() asm volatile("cp.async.commit_group;" ::: "memory")
#define CP_WAIT1()  asm volatile("cp.async.wait_group 1;" ::: "memory")
#define CP_WAIT0()  asm volatile("cp.async.wait_group 0;" ::: "memory")

__device__ __forceinline__ void ldsm4(uint32_t* r, uint32_t addr) {
    asm volatile("ldmatrix.sync.aligned.m8n8.x4.shared.b16 {%0,%1,%2,%3}, [%4];"
                 : "=r"(r[0]), "=r"(r[1]), "=r"(r[2]), "=r"(r[3]) : "r"(addr));
}

__device__ __forceinline__ uint32_t pack2h(float a, float b) {
    __half2 h = __floats2half2_rn(a, b);
    return *reinterpret_cast<uint32_t*>(&h);
}

__device__ __forceinline__ void mma_f16(float* d, const uint32_t* a, const uint32_t* b) {
    asm volatile("mma.sync.aligned.m16n8k16.row.col.f32.f16.f16.f32 "
                 "{%0,%1,%2,%3},{%4,%5,%6,%7},{%8,%9},{%0,%1,%2,%3};"
                 : "+f"(d[0]), "+f"(d[1]), "+f"(d[2]), "+f"(d[3])
                 : "r"(a[0]), "r"(a[1]), "r"(a[2]), "r"(a[3]), "r"(b[0]), "r"(b[1]));
}

// --- pre-kernel: W fp32 -> fp16 (rne), 8 elems/thread ---
__global__ void __launch_bounds__(256) wconv_kernel(const float* __restrict__ w) {
    const int i = (blockIdx.x * 256 + threadIdx.x) * 8;
    const float4 v0 = *reinterpret_cast<const float4*>(w + i);
    const float4 v1 = *reinterpret_cast<const float4*>(w + i + 4);
    uint4 o = make_uint4(pack2h(v0.x, v0.y), pack2h(v0.z, v0.w),
                         pack2h(v1.x, v1.y), pack2h(v1.z, v1.w));
    *reinterpret_cast<uint4*>(g_wh + i) = o;
}

__global__ void __launch_bounds__(256, 1)
ping_head_kernel(const float* __restrict__ x,
                 const float* __restrict__ b_ih,
                 const float* __restrict__ b_hh,
                 const float* __restrict__ lin_w,
                 const float* __restrict__ lin_b,
                 float* __restrict__ out) {
    extern __shared__ char dsm[];
    __shared__ float s_br[128], s_bz[128], s_bni[128], s_bnh[128], s_lw[128];

    const int tid = threadIdx.x;
    const int wid = tid >> 5;
    const int lane = tid & 31;
    const int m0 = blockIdx.x * 128;

    const uint32_t dsm_u = smem_u32(dsm);
    const uint32_t sb = (dsm_u + 1023u) & ~1023u;   // 1KB-aligned smem base
    char* sb_ptr = dsm + (sb - dsm_u);

    if (tid < 128) {
        s_br[tid]  = b_ih[tid] + b_hh[tid];
        s_bz[tid]  = b_ih[128 + tid] + b_hh[128 + tid];
        s_bni[tid] = b_ih[256 + tid];
        s_bnh[tid] = b_hh[256 + tid];
        s_lw[tid]  = lin_w[tid];
    }

    // ---- stage copy: A = LDG fp32 -> cvt fp16 -> STS ; B = raw cp.async ----
    // A per chunk: 128 rows x 64 f32. thread -> (row = tid>>1, half = tid&1).
    const int a_row  = tid >> 1;
    const int a_half = tid & 1;

    auto copy_stage = [&](int kc) {
        const uint32_t sbase = sb + (uint32_t)(kc % 3) * STAGE_BYTES;
        const int koff = kc * 64;

        // 1) issue A LDGs (32 consecutive floats per thread)
        const float* asrc = x + (size_t)(m0 + a_row) * 1024 + koff + a_half * 32;
        float4 f[8];
#pragma unroll
        for (int i = 0; i < 8; i++)
            f[i] = *reinterpret_cast<const float4*>(asrc + i * 4);

        // 2) B cp.async while A LDGs are in flight
        const uint32_t bbase = sbase + (uint32_t)A_BYTES;
#pragma unroll
        for (int ch = 0; ch < 12; ch++) {
            const int bi = tid + ch * 256;
            const int row = bi >> 3, c = bi & 7;
            const uint32_t doff = (uint32_t)(row * 128) +
                                  (((uint32_t)(c * 16)) ^ ((uint32_t)(row & 7) << 4));
            cp_async16(bbase + doff, g_wh + (size_t)row * 1024 + koff + c * 8);
        }

        // 3) cvt + STS A (swizzled)
        char* sA = sb_ptr + (kc % 3) * STAGE_BYTES;
#pragma unroll
        for (int i = 0; i < 4; i++) {
            uint4 o = make_uint4(pack2h(f[2*i].x, f[2*i].y),   pack2h(f[2*i].z, f[2*i].w),
                                 pack2h(f[2*i+1].x, f[2*i+1].y), pack2h(f[2*i+1].z, f[2*i+1].w));
            const uint32_t doff = (uint32_t)(a_row * 128) +
                                  (((uint32_t)(a_half * 64 + i * 16)) ^ ((uint32_t)(a_row & 7) << 4));
            *reinterpret_cast<uint4*>(sA + doff) = o;
        }
    };

    // ---- per-thread ldmatrix addressing (2m x 4n warp grid) ----
    const int warp_m = wid >> 2;
    const int warp_n = wid & 3;
    const int mb = warp_m * 64;
    const int nb = warp_n * 96;

    const int ri = lane & 15;
    const uint32_t sega = (uint32_t)((lane >> 4) << 4);
    const uint32_t xpa  = (uint32_t)((ri & 7) << 4);
    const uint32_t a_root = (uint32_t)((mb + ri) * 128);

    const int rb = (lane & 7) + (((lane >> 4) & 1) << 3);
    const uint32_t segb = (uint32_t)(((lane >> 3) & 1) << 4);
    const uint32_t xpb  = (uint32_t)((rb & 7) << 4);
    const uint32_t b_root = (uint32_t)A_BYTES + (uint32_t)((nb + rb) * 128);

    float acc[4][12][4];
#pragma unroll
    for (int t = 0; t < 4; t++)
#pragma unroll
        for (int j = 0; j < 12; j++)
#pragma unroll
            for (int q = 0; q < 4; q++) acc[t][j][q] = 0.0f;

    copy_stage(0); CP_COMMIT();
    copy_stage(1); CP_COMMIT();

    for (int kc = 0; kc < KCHUNKS; kc++) {
        CP_WAIT1();
        __syncthreads();
        if (kc + 2 < KCHUNKS) copy_stage(kc + 2);
        CP_COMMIT();

        const uint32_t stb = sb + (uint32_t)(kc % 3) * STAGE_BYTES;
#pragma unroll
        for (int s = 0; s < 4; s++) {
            const uint32_t sbytes = (uint32_t)(s * 32);   // k16 = 32B of halves
            uint32_t af[4][4];
#pragma unroll
            for (int t = 0; t < 4; t++) {
                ldsm4(af[t], stb + a_root + (uint32_t)(t * 2048) + ((sbytes + sega) ^ xpa));
            }
#pragma unroll
            for (int jp = 0; jp < 6; jp++) {
                uint32_t bf[4];
                ldsm4(bf, stb + b_root + (uint32_t)(jp * 2048) + ((sbytes + segb) ^ xpb));
#pragma unroll
                for (int t = 0; t < 4; t++) {
                    mma_f16(acc[t][2 * jp],     af[t], bf);
                    mma_f16(acc[t][2 * jp + 1], af[t], bf + 2);
                }
            }
        }
    }

    CP_WAIT0();
    __syncthreads();

    // ---- spill gi to smem ----
    float* gi = reinterpret_cast<float*>(sb_ptr);
    {
        const int r0 = mb + (lane >> 2);
        const int c0 = nb + 2 * (lane & 3);
#pragma unroll
        for (int t = 0; t < 4; t++) {
            const int row = r0 + t * 16;
#pragma unroll
            for (int j = 0; j < 12; j++) {
                const int col = c0 + j * 8;
                gi[row * ROWP + col]           = acc[t][j][0];
                gi[row * ROWP + col + 1]       = acc[t][j][1];
                gi[(row + 8) * ROWP + col]     = acc[t][j][2];
                gi[(row + 8) * ROWP + col + 1] = acc[t][j][3];
            }
        }
    }
    __syncthreads();

    // ---- fused gate epilogue: 2 threads per row ----
    {
        const int row = tid >> 1;
        const int half = tid & 1;
        const float* gr = gi + row * ROWP;
        float a = 0.0f;
#pragma unroll 4
        for (int k = 0; k < 64; k++) {
            const int g = 2 * k + half;
            const float xr = gr[g] + s_br[g];
            const float xz = gr[128 + g] + s_bz[g];
            const float r  = 1.0f / (1.0f + __expf(-xr));
            const float zc = 1.0f / (1.0f + __expf(xz));          // 1 - z
            const float xn = gr[256 + g] + s_bni[g] + r * s_bnh[g];
            const float e  = __expf(-2.0f * fabsf(xn));
            float th = __fdividef(1.0f - e, 1.0f + e);
            th = copysignf(th, xn);
            a += s_lw[g] * zc * th;
        }
        a += __shfl_xor_sync(0xffffffffu, a, 1);
        if (half == 0) out[m0 + row] = a + lin_b[0];
    }
}

extern "C" void kernel_launch(void* const* d_in, const int* in_sizes, int n_in,
                              void* d_out, int out_size) {
    const float* x     = (const float*)d_in[0];
    const float* w_ih  = (const float*)d_in[1];
    // d_in[2] = weight_hh: mathematically dead (hidden state is always zero)
    const float* b_ih  = (const float*)d_in[3];
    const float* b_hh  = (const float*)d_in[4];
    const float* lin_w = (const float*)d_in[5];
    const float* lin_b = (const float*)d_in[6];
    float* out = (float*)d_out;

    wconv_kernel<<<192, 256>>>(w_ih);   // 384*1024 / (256*8)

    cudaFuncSetAttribute(ping_head_kernel,
                         cudaFuncAttributeMaxDynamicSharedMemorySize, SMEM_DYN);
    ping_head_kernel<<<512, 256, SMEM_DYN>>>(x, b_ih, b_hh, lin_w, lin_b, out);
}

// round 8
// speedup vs baseline: 1.2220x; 1.1292x over previous
#include <cuda_runtime.h>
#include <cuda_fp16.h>
#include <cstdint>

// ---------------------------------------------------------------------------
// PingHead on sm_103 (legacy mma.sync path, fp16 operands / fp32 accum).
// gi = x @ W_ih^T : M=65536, N=384, K=1024 ; fused GRU-gate epilogue.
// R8: 2 CTAs per SM (M_TILE=64, 96 acc regs/thread, launch_bounds(256,2)).
// Independent CTA phases cover each other's copy/barrier bubbles.
// K chunk = 32 halves (64B rows, 2-bit XOR swizzle), 3-stage cp.async ring.
// W pre-converted to fp16 (rne); x converted LDG->cvt->STS in copy phase.
// ---------------------------------------------------------------------------

#define M_TILE 64
#define KCHUNKS 32
#define A_ST 4096                            // 64 rows x 64B
#define B_ST 24576                           // 384 rows x 64B
#define STAGE_BYTES (A_ST + B_ST)            // 28672
#define NSTAGE 3
#define RING_BYTES (NSTAGE * STAGE_BYTES)    // 86016
#define ROWP 385
#define GI_BYTES (M_TILE * ROWP * 4)         // 98560
#define BIAS_OFF GI_BYTES                    // biases after gi region
#define BIAS_BYTES (5 * 128 * 4)
#define SMEM_DYN (BIAS_OFF + BIAS_BYTES + 1024)

__device__ __half g_wh[384 * 1024];          // W_ih pre-converted to fp16 (rne)

__device__ __forceinline__ uint32_t smem_u32(const void* p) {
    uint32_t a;
    asm("{ .reg .u64 t; cvta.to.shared.u64 t, %1; cvt.u32.u64 %0, t; }" : "=r"(a) : "l"(p));
    return a;
}

__device__ __forceinline__ void cp_async16(uint32_t dst, const void* src) {
    asm volatile("cp.async.cg.shared.global [%0], [%1], 16;" :: "r"(dst), "l"(src) : "memory");
}
#define CP_COMMIT() asm volatile("cp.async.commit_group;" ::: "memory")
#define CP_WAIT1()  asm volatile("cp.async.wait_group 1;" ::: "memory")
#define CP_WAIT0()  asm volatile("cp.async.wait_group 0;" ::: "memory")

__device__ __forceinline__ void ldsm4(uint32_t* r, uint32_t addr) {
    asm volatile("ldmatrix.sync.aligned.m8n8.x4.shared.b16 {%0,%1,%2,%3}, [%4];"
                 : "=r"(r[0]), "=r"(r[1]), "=r"(r[2]), "=r"(r[3]) : "r"(addr));
}

__device__ __forceinline__ uint32_t pack2h(float a, float b) {
    __half2 h = __floats2half2_rn(a, b);
    return *reinterpret_cast<uint32_t*>(&h);
}

__device__ __forceinline__ void mma_f16(float* d, const uint32_t* a, const uint32_t* b) {
    asm volatile("mma.sync.aligned.m16n8k16.row.col.f32.f16.f16.f32 "
                 "{%0,%1,%2,%3},{%4,%5,%6,%7},{%8,%9},{%0,%1,%2,%3};"
                 : "+f"(d[0]), "+f"(d[1]), "+f"(d[2]), "+f"(d[3])
                 : "r"(a[0]), "r"(a[1]), "r"(a[2]), "r"(a[3]), "r"(b[0]), "r"(b[1]));
}

// --- pre-kernel: W fp32 -> fp16 (rne) ---
__global__ void __launch_bounds__(256) wconv_kernel(const float* __restrict__ w) {
    const int i = (blockIdx.x * 256 + threadIdx.x) * 8;
    const float4 v0 = *reinterpret_cast<const float4*>(w + i);
    const float4 v1 = *reinterpret_cast<const float4*>(w + i + 4);
    uint4 o = make_uint4(pack2h(v0.x, v0.y), pack2h(v0.z, v0.w),
                         pack2h(v1.x, v1.y), pack2h(v1.z, v1.w));
    *reinterpret_cast<uint4*>(g_wh + i) = o;
}

__global__ void __launch_bounds__(256, 2)
ping_head_kernel(const float* __restrict__ x,
                 const float* __restrict__ b_ih,
                 const float* __restrict__ b_hh,
                 const float* __restrict__ lin_w,
                 const float* __restrict__ lin_b,
                 float* __restrict__ out) {
    extern __shared__ char dsm[];

    const int tid = threadIdx.x;
    const int wid = tid >> 5;
    const int lane = tid & 31;
    const int m0 = blockIdx.x * M_TILE;

    const uint32_t sb = smem_u32(dsm);     // harness smem is 1KB-aligned anyway
    char* sb_ptr = dsm;

    // biases in dynamic smem tail (beyond ring and gi regions; persists)
    float* s_br  = reinterpret_cast<float*>(dsm + BIAS_OFF);
    float* s_bz  = s_br + 128;
    float* s_bni = s_bz + 128;
    float* s_bnh = s_bni + 128;
    float* s_lw  = s_bnh + 128;
    if (tid < 128) {
        s_br[tid]  = b_ih[tid] + b_hh[tid];
        s_bz[tid]  = b_ih[128 + tid] + b_hh[128 + tid];
        s_bni[tid] = b_ih[256 + tid];
        s_bnh[tid] = b_hh[256 + tid];
        s_lw[tid]  = lin_w[tid];
    }

    // ---- stage copy: A = LDG fp32 -> cvt -> STS ; B = raw cp.async ----
    // A per chunk: 64 rows x 32 f32 = 8 floats/thread (row = tid>>2, sub = tid&3)
    const int a_row = tid >> 2;
    const int a_sub = tid & 3;

    auto copy_stage = [&](int kc) {
        const int st = kc % 3;
        const int koff = kc * 32;

        // A: 2 float4 LDG -> 8 halves -> 1 uint4 STS (swizzled 64B rows)
        const float* asrc = x + (size_t)(m0 + a_row) * 1024 + koff + a_sub * 8;
        const float4 f0 = *reinterpret_cast<const float4*>(asrc);
        const float4 f1 = *reinterpret_cast<const float4*>(asrc + 4);

        // B: 384 rows x 32 halves = 1536 x 16B, 6 per thread
        const uint32_t bbase = sb + (uint32_t)(st * STAGE_BYTES + A_ST);
#pragma unroll
        for (int ch = 0; ch < 6; ch++) {
            const int bi = tid + ch * 256;
            const int row = bi >> 2, c = bi & 3;
            const uint32_t doff = (uint32_t)(row * 64) +
                                  (((uint32_t)(c * 16)) ^ ((uint32_t)(row & 3) << 4));
            cp_async16(bbase + doff, g_wh + (size_t)row * 1024 + koff + c * 8);
        }

        uint4 o = make_uint4(pack2h(f0.x, f0.y), pack2h(f0.z, f0.w),
                             pack2h(f1.x, f1.y), pack2h(f1.z, f1.w));
        const uint32_t adoff = (uint32_t)(a_row * 64) +
                               (((uint32_t)(a_sub * 16)) ^ ((uint32_t)(a_row & 3) << 4));
        *reinterpret_cast<uint4*>(sb_ptr + st * STAGE_BYTES + adoff) = o;
    };

    // ---- ldmatrix addressing: 2m x 4n warp grid, warp tile 32m x 96n ----
    const int warp_m = wid >> 2;          // 0..1
    const int warp_n = wid & 3;           // 0..3
    const int mb = warp_m * 32;
    const int nb = warp_n * 96;

    const int ri = lane & 15;
    const uint32_t sega = (uint32_t)((lane >> 4) << 4);
    const uint32_t xpa  = (uint32_t)((ri & 3) << 4);
    const uint32_t a_root = (uint32_t)((mb + ri) * 64);

    const int rb = (lane & 7) + (((lane >> 4) & 1) << 3);
    const uint32_t segb = (uint32_t)(((lane >> 3) & 1) << 4);
    const uint32_t xpb  = (uint32_t)((rb & 3) << 4);
    const uint32_t b_root = (uint32_t)A_ST + (uint32_t)((nb + rb) * 64);

    float acc[2][12][4];
#pragma unroll
    for (int t = 0; t < 2; t++)
#pragma unroll
        for (int j = 0; j < 12; j++)
#pragma unroll
            for (int q = 0; q < 4; q++) acc[t][j][q] = 0.0f;

    copy_stage(0); CP_COMMIT();
    copy_stage(1); CP_COMMIT();

    for (int kc = 0; kc < KCHUNKS; kc++) {
        CP_WAIT1();
        __syncthreads();
        if (kc + 2 < KCHUNKS) copy_stage(kc + 2);
        CP_COMMIT();

        const uint32_t stb = sb + (uint32_t)((kc % 3) * STAGE_BYTES);
#pragma unroll
        for (int s = 0; s < 2; s++) {
            const uint32_t sbytes = (uint32_t)(s * 32);   // k16 = 32B of halves
            uint32_t af[2][4];
            ldsm4(af[0], stb + a_root + ((sbytes + sega) ^ xpa));
            ldsm4(af[1], stb + a_root + 1024u + ((sbytes + sega) ^ xpa));
#pragma unroll
            for (int jp = 0; jp < 6; jp++) {
                uint32_t bf[4];
                ldsm4(bf, stb + b_root + (uint32_t)(jp * 1024) + ((sbytes + segb) ^ xpb));
                mma_f16(acc[0][2 * jp],     af[0], bf);
                mma_f16(acc[0][2 * jp + 1], af[0], bf + 2);
                mma_f16(acc[1][2 * jp],     af[1], bf);
                mma_f16(acc[1][2 * jp + 1], af[1], bf + 2);
            }
        }
    }

    CP_WAIT0();
    __syncthreads();

    // ---- spill gi to smem (64 x ROWP) ----
    float* gi = reinterpret_cast<float*>(sb_ptr);
    {
        const int r0 = mb + (lane >> 2);
        const int c0 = nb + 2 * (lane & 3);
#pragma unroll
        for (int t = 0; t < 2; t++) {
            const int row = r0 + t * 16;
#pragma unroll
            for (int j = 0; j < 12; j++) {
                const int col = c0 + j * 8;
                gi[row * ROWP + col]           = acc[t][j][0];
                gi[row * ROWP + col + 1]       = acc[t][j][1];
                gi[(row + 8) * ROWP + col]     = acc[t][j][2];
                gi[(row + 8) * ROWP + col + 1] = acc[t][j][3];
            }
        }
    }
    __syncthreads();

    // ---- fused gate epilogue: 4 threads per row ----
    {
        const int row = tid >> 2;
        const int qtr = tid & 3;
        const float* gr = gi + row * ROWP;
        float a = 0.0f;
#pragma unroll 4
        for (int k = 0; k < 32; k++) {
            const int g = qtr * 32 + k;
            const float xr = gr[g] + s_br[g];
            const float xz = gr[128 + g] + s_bz[g];
            const float r  = 1.0f / (1.0f + __expf(-xr));
            const float zc = 1.0f / (1.0f + __expf(xz));          // 1 - z
            const float xn = gr[256 + g] + s_bni[g] + r * s_bnh[g];
            const float e  = __expf(-2.0f * fabsf(xn));
            float th = __fdividef(1.0f - e, 1.0f + e);
            th = copysignf(th, xn);
            a += s_lw[g] * zc * th;
        }
        a += __shfl_xor_sync(0xffffffffu, a, 1);
        a += __shfl_xor_sync(0xffffffffu, a, 2);
        if (qtr == 0) out[m0 + row] = a + lin_b[0];
    }
}

extern "C" void kernel_launch(void* const* d_in, const int* in_sizes, int n_in,
                              void* d_out, int out_size) {
    const float* x     = (const float*)d_in[0];
    const float* w_ih  = (const float*)d_in[1];
    // d_in[2] = weight_hh: mathematically dead (hidden state is always zero)
    const float* b_ih  = (const float*)d_in[3];
    const float* b_hh  = (const float*)d_in[4];
    const float* lin_w = (const float*)d_in[5];
    const float* lin_b = (const float*)d_in[6];
    float* out = (float*)d_out;

    wconv_kernel<<<192, 256>>>(w_ih);   // 384*1024 / (256*8)

    cudaFuncSetAttribute(ping_head_kernel,
                         cudaFuncAttributeMaxDynamicSharedMemorySize, SMEM_DYN);
    ping_head_kernel<<<1024, 256, SMEM_DYN>>>(x, b_ih, b_hh, lin_w, lin_b, out);
}